// round 14
// baseline (speedup 1.0000x reference)
#include <cuda_runtime.h>
#include <cuda_bf16.h>
#include <cstdint>

#define NROWS 65536
#define NDIMS 512
#define KDIM  512
#define MKNOT 200
#define LUTN  1024
#define LUT_SCALE (1024.0f / 12.0f)

// ---------------------------------------------------------------------------
// Device scratch (allocation-free)
// ---------------------------------------------------------------------------
__device__ __align__(16) float         g_x[(size_t)KDIM * NROWS];       // data0^T (K x N)
__device__ __align__(16) __nv_bfloat16 g_data_hi[(size_t)NROWS * NDIMS];
__device__ __align__(16) __nv_bfloat16 g_data_lo[(size_t)NROWS * NDIMS];
__device__ __align__(16) __nv_bfloat16 g_t_hi[(size_t)KDIM * NROWS];    // (K x N)
__device__ __align__(16) __nv_bfloat16 g_t_lo[(size_t)KDIM * NROWS];
__device__ __align__(16) __nv_bfloat16 g_A_hi[KDIM * NDIMS];            // [d][k]
__device__ __align__(16) __nv_bfloat16 g_A_lo[KDIM * NDIMS];
__device__ __align__(16) __nv_bfloat16 g_AT_hi[KDIM * NDIMS];           // [k][d]
__device__ __align__(16) __nv_bfloat16 g_AT_lo[KDIM * NDIMS];
__device__ __align__(16) float         g_partial[64 * NROWS];
__device__ __align__(16) uint8_t       g_lut[(size_t)KDIM * LUTN];

// ---------------------------------------------------------------------------
// PTX helpers (sm_80-level: legal on baseline compute_103 target)
// ---------------------------------------------------------------------------
__device__ __forceinline__ uint32_t smem_u32(const void* p) {
    uint32_t a;
    asm("{ .reg .u64 t; cvta.to.shared.u64 t, %1; cvt.u32.u64 %0, t; }" : "=r"(a) : "l"(p));
    return a;
}
#define CP_ASYNC16(dst, src) \
    asm volatile("cp.async.cg.shared.global [%0], [%1], 16;" :: "r"(dst), "l"(src))
#define CP_COMMIT() asm volatile("cp.async.commit_group;" ::: "memory")
#define CP_WAIT(n)  asm volatile("cp.async.wait_group %0;" :: "n"(n) : "memory")

__device__ __forceinline__ void ldsm_x4(uint32_t* r, uint32_t addr) {
    asm volatile("ldmatrix.sync.aligned.m8n8.x4.shared.b16 {%0,%1,%2,%3}, [%4];"
                 : "=r"(r[0]), "=r"(r[1]), "=r"(r[2]), "=r"(r[3]) : "r"(addr));
}
__device__ __forceinline__ void ldsm_x4_trans(uint32_t* r, uint32_t addr) {
    asm volatile("ldmatrix.sync.aligned.m8n8.x4.trans.shared.b16 {%0,%1,%2,%3}, [%4];"
                 : "=r"(r[0]), "=r"(r[1]), "=r"(r[2]), "=r"(r[3]) : "r"(addr));
}
__device__ __forceinline__ void mma16816(float* d, const uint32_t* a, const uint32_t* b) {
    asm volatile(
        "mma.sync.aligned.m16n8k16.row.col.f32.bf16.bf16.f32 "
        "{%0,%1,%2,%3}, {%4,%5,%6,%7}, {%8,%9}, {%0,%1,%2,%3};"
        : "+f"(d[0]), "+f"(d[1]), "+f"(d[2]), "+f"(d[3])
        : "r"(a[0]), "r"(a[1]), "r"(a[2]), "r"(a[3]), "r"(b[0]), "r"(b[1]));
}

// ---------------------------------------------------------------------------
// Split decomposition
// ---------------------------------------------------------------------------
__global__ __launch_bounds__(256) void decomp_data_kernel(const float* __restrict__ data) {
    size_t i = ((size_t)blockIdx.x * 256 + threadIdx.x) * 4;
    float4 v = *reinterpret_cast<const float4*>(data + i);
    __nv_bfloat16 h0 = __float2bfloat16(v.x), h1 = __float2bfloat16(v.y);
    __nv_bfloat16 h2 = __float2bfloat16(v.z), h3 = __float2bfloat16(v.w);
    __nv_bfloat16 l0 = __float2bfloat16(v.x - __bfloat162float(h0));
    __nv_bfloat16 l1 = __float2bfloat16(v.y - __bfloat162float(h1));
    __nv_bfloat16 l2 = __float2bfloat16(v.z - __bfloat162float(h2));
    __nv_bfloat16 l3 = __float2bfloat16(v.w - __bfloat162float(h3));
    *reinterpret_cast<__nv_bfloat162*>(g_data_hi + i)     = __nv_bfloat162(h0, h1);
    *reinterpret_cast<__nv_bfloat162*>(g_data_hi + i + 2) = __nv_bfloat162(h2, h3);
    *reinterpret_cast<__nv_bfloat162*>(g_data_lo + i)     = __nv_bfloat162(l0, l1);
    *reinterpret_cast<__nv_bfloat162*>(g_data_lo + i + 2) = __nv_bfloat162(l2, l3);
}

__global__ __launch_bounds__(256) void decomp_A_kernel(const float* __restrict__ A) {
    int i = blockIdx.x * 256 + threadIdx.x;
    float v = A[i];
    __nv_bfloat16 h = __float2bfloat16(v);
    __nv_bfloat16 l = __float2bfloat16(v - __bfloat162float(h));
    g_A_hi[i] = h;
    g_A_lo[i] = l;
    int d = i >> 9, k = i & 511;
    g_AT_hi[k * 512 + d] = h;
    g_AT_lo[k * 512 + d] = l;
}

// ---------------------------------------------------------------------------
// LUT build
// ---------------------------------------------------------------------------
__global__ __launch_bounds__(256) void lut_kernel(const float* __restrict__ xx) {
    __shared__ float sx[MKNOT];
    const int k = blockIdx.x;
    const int tid = threadIdx.x;
    if (tid < MKNOT) sx[tid] = xx[(size_t)k * MKNOT + tid];
    __syncthreads();
    for (int j = tid; j < LUTN; j += 256) {
        const float gx = -4.0f + (float)j * (12.0f / LUTN);
        int lo = 0, hi = MKNOT;
        while (lo < hi) {
            int mid = (lo + hi) >> 1;
            if (sx[mid] < gx) lo = mid + 1; else hi = mid;
        }
        g_lut[(size_t)k * LUTN + j] = (uint8_t)lo;
    }
}

// ---------------------------------------------------------------------------
// HMMA GEMM mainloop, phase-paired: D[128,128] over K'=1536 in 16 chunks.
// TB=false: B from (N,K) K-major rows (gemm1, B = AT).
// TB=true : B from (K,N), 64 k-rows x 256B tiles, ldmatrix.trans (gemm2, B = t).
// ---------------------------------------------------------------------------
#define STAGE_BYTES 49152
#define GEMM_SMEM   (2 * STAGE_BYTES)

template <bool TB>
__device__ __forceinline__ void issue_chunk(uint32_t sbase, int buf, int c, int tid,
        const __nv_bfloat16* aHi, const __nv_bfloat16* aLo,
        const __nv_bfloat16* bHi, const __nv_bfloat16* bLo) {
    const bool dual = (c < 8);
    const int koff = (c & 7) * 64;
    const __nv_bfloat16* a = dual ? aHi : aLo;
    uint32_t abase = sbase + buf * STAGE_BYTES;
    uint32_t bbase = abase + 16384;
    #pragma unroll
    for (int it = 0; it < 4; ++it) {          // A tile: 128 rows x 128B (K-major)
        int i = tid + it * 256;
        int r = i >> 3, cc = i & 7;
        CP_ASYNC16(abase + r * 128 + ((cc ^ (r & 7)) << 4),
                   a + (size_t)r * 512 + koff + cc * 8);
    }
    if (!TB) {
        #pragma unroll
        for (int it = 0; it < 4; ++it) {      // B-hi: 128 n-rows x 128B
            int i = tid + it * 256;
            int r = i >> 3, cc = i & 7;
            CP_ASYNC16(bbase + r * 128 + ((cc ^ (r & 7)) << 4),
                       bHi + (size_t)r * 512 + koff + cc * 8);
        }
        if (dual) {
            #pragma unroll
            for (int it = 0; it < 4; ++it) {
                int i = tid + it * 256;
                int r = i >> 3, cc = i & 7;
                CP_ASYNC16(bbase + 16384 + r * 128 + ((cc ^ (r & 7)) << 4),
                           bLo + (size_t)r * 512 + koff + cc * 8);
            }
        }
    } else {
        #pragma unroll
        for (int it = 0; it < 4; ++it) {      // B-hi: 64 k-rows x 256B from (K,N)
            int i = tid + it * 256;
            int r = i >> 4, cc = i & 15;
            CP_ASYNC16(bbase + r * 256 + ((cc ^ (r & 7)) << 4),
                       bHi + (size_t)(koff + r) * NROWS + cc * 8);
        }
        if (dual) {
            #pragma unroll
            for (int it = 0; it < 4; ++it) {
                int i = tid + it * 256;
                int r = i >> 4, cc = i & 15;
                CP_ASYNC16(bbase + 16384 + r * 256 + ((cc ^ (r & 7)) << 4),
                           bLo + (size_t)(koff + r) * NROWS + cc * 8);
            }
        }
    }
}

template <bool TB>
__device__ __forceinline__ void load_bfrag(uint32_t bbase, int s, int lane, int wn,
                                           int grp, uint32_t bf[4][2]) {
    if (!TB) {
        #pragma unroll
        for (int nt2 = 0; nt2 < 2; ++nt2) {
            int rr = wn * 32 + nt2 * 16 + (lane & 7) + ((grp >> 1) << 3);
            int cc = s * 2 + (grp & 1);
            uint32_t tmp[4];
            ldsm_x4(tmp, bbase + rr * 128 + ((cc ^ (rr & 7)) << 4));
            bf[nt2 * 2][0] = tmp[0];     bf[nt2 * 2][1] = tmp[1];
            bf[nt2 * 2 + 1][0] = tmp[2]; bf[nt2 * 2 + 1][1] = tmp[3];
        }
    } else {
        #pragma unroll
        for (int nt2 = 0; nt2 < 2; ++nt2) {
            int rr = s * 16 + ((grp & 1) << 3) + (lane & 7);     // k-row 0..63
            int un = wn * 4 + nt2 * 2 + (grp >> 1);              // 16B n-unit 0..15
            uint32_t tmp[4];
            ldsm_x4_trans(tmp, bbase + rr * 256 + ((un ^ (rr & 7)) << 4));
            bf[nt2 * 2][0] = tmp[0];     bf[nt2 * 2][1] = tmp[1];
            bf[nt2 * 2 + 1][0] = tmp[2]; bf[nt2 * 2 + 1][1] = tmp[3];
        }
    }
}

template <bool TB>
__device__ __forceinline__ void compute_chunk(uint32_t sbase, int buf, bool dual,
                                              int lane, int wm, int wn, float acc[4][4][4]) {
    uint32_t abase = sbase + buf * STAGE_BYTES;
    uint32_t bbase = abase + 16384;
    const int grp = lane >> 3;
    #pragma unroll
    for (int s = 0; s < 4; ++s) {
        uint32_t af[4][4];
        #pragma unroll
        for (int mt = 0; mt < 4; ++mt) {
            int rr = wm * 64 + mt * 16 + (lane & 7) + ((grp & 1) << 3);
            int cc = s * 2 + (grp >> 1);
            ldsm_x4(af[mt], abase + rr * 128 + ((cc ^ (rr & 7)) << 4));
        }
        uint32_t bf[4][2];
        load_bfrag<TB>(bbase, s, lane, wn, grp, bf);
        #pragma unroll
        for (int mt = 0; mt < 4; ++mt)
            #pragma unroll
            for (int nt = 0; nt < 4; ++nt)
                mma16816(acc[mt][nt], af[mt], bf[nt]);
        if (dual) {   // reuse af against the B-lo tile
            uint32_t bf2[4][2];
            load_bfrag<TB>(bbase + 16384, s, lane, wn, grp, bf2);
            #pragma unroll
            for (int mt = 0; mt < 4; ++mt)
                #pragma unroll
                for (int nt = 0; nt < 4; ++nt)
                    mma16816(acc[mt][nt], af[mt], bf2[nt]);
        }
    }
}

template <bool TB>
__device__ __forceinline__ void gemm_mainloop(const __nv_bfloat16* aHi, const __nv_bfloat16* aLo,
                                              const __nv_bfloat16* bHi, const __nv_bfloat16* bLo,
                                              uint32_t sbase, int tid, int lane, int wm, int wn,
                                              float acc[4][4][4]) {
    #pragma unroll
    for (int mt = 0; mt < 4; ++mt)
        #pragma unroll
        for (int nt = 0; nt < 4; ++nt)
            #pragma unroll
            for (int r = 0; r < 4; ++r) acc[mt][nt][r] = 0.f;

    issue_chunk<TB>(sbase, 0, 0, tid, aHi, aLo, bHi, bLo);
    CP_COMMIT();
    int buf = 0;
    for (int c = 0; c < 16; ++c) {
        if (c + 1 < 16) {
            issue_chunk<TB>(sbase, buf ^ 1, c + 1, tid, aHi, aLo, bHi, bLo);
            CP_COMMIT();
            CP_WAIT(1);
        } else {
            CP_WAIT(0);
        }
        __syncthreads();
        compute_chunk<TB>(sbase, buf, c < 8, lane, wm, wn, acc);
        __syncthreads();
        buf ^= 1;
    }
}

// Stage one 64-column half of D into smem as sD[c][m] stride 132.
__device__ __forceinline__ void stage_half(float* sD, const float acc[4][4][4],
                                           int wm, int wn, int lane, int half) {
    if ((wn >> 1) == half) {
        #pragma unroll
        for (int mt = 0; mt < 4; ++mt)
            #pragma unroll
            for (int nt = 0; nt < 4; ++nt) {
                int r0 = wm * 64 + mt * 16 + (lane >> 2);
                int c0 = (wn & 1) * 32 + nt * 8 + (lane & 3) * 2;
                sD[(c0    ) * 132 + r0    ] = acc[mt][nt][0];
                sD[(c0 + 1) * 132 + r0    ] = acc[mt][nt][1];
                sD[(c0    ) * 132 + r0 + 8] = acc[mt][nt][2];
                sD[(c0 + 1) * 132 + r0 + 8] = acc[mt][nt][3];
            }
    }
}

__global__ __launch_bounds__(256, 2) void gemm1_kernel() {
    extern __shared__ char smem[];
    const int k0 = blockIdx.x * 128;
    const int n0 = blockIdx.y * 128;
    const int tid = threadIdx.x;
    const int lane = tid & 31, wid = tid >> 5;
    const int wm = wid & 1, wn = wid >> 1;
    uint32_t sbase = smem_u32(smem);

    float acc[4][4][4];
    gemm_mainloop<false>(g_data_hi + (size_t)n0 * 512, g_data_lo + (size_t)n0 * 512,
                         g_AT_hi + (size_t)k0 * 512, g_AT_lo + (size_t)k0 * 512,
                         sbase, tid, lane, wm, wn, acc);

    float* sD = (float*)smem;
    #pragma unroll
    for (int half = 0; half < 2; ++half) {
        stage_half(sD, acc, wm, wn, lane, half);
        __syncthreads();
        #pragma unroll
        for (int it = 0; it < 8; ++it) {
            int idx = tid + it * 256;
            int nn = idx >> 5, mm = (idx & 31) * 4;
            float4 v = *reinterpret_cast<const float4*>(sD + nn * 132 + mm);
            *reinterpret_cast<float4*>(&g_x[(size_t)(k0 + half * 64 + nn) * NROWS + n0 + mm]) = v;
        }
        __syncthreads();
    }
}

__global__ __launch_bounds__(256, 2) void gemm2_kernel(const float* __restrict__ data,
                                                       float* __restrict__ out) {
    extern __shared__ char smem[];
    const int d0 = blockIdx.x * 128;
    const int n0 = blockIdx.y * 128;
    const int tid = threadIdx.x;
    const int lane = tid & 31, wid = tid >> 5;
    const int wm = wid & 1, wn = wid >> 1;
    uint32_t sbase = smem_u32(smem);

    float acc[4][4][4];
    gemm_mainloop<true>(g_A_hi + (size_t)d0 * 512, g_A_lo + (size_t)d0 * 512,
                        g_t_hi + n0, g_t_lo + n0,
                        sbase, tid, lane, wm, wn, acc);

    float* sD = (float*)smem;
    #pragma unroll
    for (int half = 0; half < 2; ++half) {
        stage_half(sD, acc, wm, wn, lane, half);
        __syncthreads();
        #pragma unroll
        for (int it = 0; it < 8; ++it) {
            int idx = tid + it * 256;
            int nn = idx >> 5, mm = (idx & 31) * 4;
            size_t gi = (size_t)(n0 + half * 64 + nn) * NDIMS + d0 + mm;
            float4 v = *reinterpret_cast<const float4*>(sD + nn * 132 + mm);
            float4 dv = *reinterpret_cast<const float4*>(data + gi);
            v.x += dv.x; v.y += dv.y; v.z += dv.z; v.w += dv.w;
            *reinterpret_cast<float4*>(out + gi) = v;
        }
        __syncthreads();
    }
}

// ---------------------------------------------------------------------------
// Spline v4: block = 8 k x 1024 n (4 s-iters of 256 n, thread = one n, loops k).
// MUFU-lean: reciprocals instead of divides; one logf per 8-k derivative
// product (r_k bounded in ~[0.05, 60] so the 8-product stays in fp32 range).
// ---------------------------------------------------------------------------
__global__ __launch_bounds__(256) void spline_kernel(const float* __restrict__ xx,
                                                     const float* __restrict__ yy,
                                                     const float* __restrict__ delta) {
    __shared__ float sxx[8 * MKNOT], syy[8 * MKNOT], sdl[8 * MKNOT];
    __shared__ uint8_t slut[8 * LUTN];

    const int kg = blockIdx.x;          // 0..63
    const int ng = blockIdx.y;          // 0..63
    const int k0 = kg * 8;
    const int tid = threadIdx.x;

    for (int i = tid; i < 8 * MKNOT; i += 256) {
        int kl = i / MKNOT, m = i - kl * MKNOT;
        size_t gi = (size_t)(k0 + kl) * MKNOT + m;
        sxx[i] = xx[gi]; syy[i] = yy[gi]; sdl[i] = delta[gi];
    }
    for (int i = tid; i < (8 * LUTN) / 4; i += 256)
        reinterpret_cast<uint32_t*>(slut)[i] =
            reinterpret_cast<const uint32_t*>(g_lut + (size_t)k0 * LUTN)[i];
    __syncthreads();

    for (int s = 0; s < 4; ++s) {
        const int n = ng * 1024 + s * 256 + tid;
        float prod = 1.f;
        #pragma unroll 4
        for (int kl = 0; kl < 8; ++kl) {
            const float* kx = sxx + kl * MKNOT;
            const float* ky = syy + kl * MKNOT;
            const float* kd = sdl + kl * MKNOT;
            const size_t gidx = (size_t)(k0 + kl) * NROWS + n;
            const float x = g_x[gidx];

            int j = __float2int_rd((x + 4.0f) * LUT_SCALE);
            j = min(max(j, 0), LUTN - 1);
            int idx = (int)slut[kl * LUTN + j];
            if (idx < MKNOT && kx[idx] < x) ++idx;

            const bool below = (idx == 0);
            const bool above = (idx == MKNOT);
            const int b = min(max(idx, 1), MKNOT - 1) - 1;

            const float xk = kx[b], xk1 = kx[b + 1];
            const float yk = ky[b], yk1 = ky[b + 1];
            const float dk = kd[b], dk1 = kd[b + 1];
            const float dxk = xk1 - xk;
            const float dyk = yk1 - yk;
            const float rcp_dx = __fdividef(1.f, dxk);
            const float sl = dyk * rcp_dx;
            float xi = (x - xk) * rcp_dx;
            xi = fminf(fmaxf(xi, 0.f), 1.f);
            const float xi1 = 1.f - xi;
            const float denom = sl + (dk1 + dk - 2.f * sl) * xi * xi1;
            const float rcp_den = __fdividef(1.f, denom);
            float y = yk + dyk * (sl * xi * xi + dk * xi * xi1) * rcp_den;
            const float num = dk1 * xi * xi + 2.f * sl * xi * xi1 + dk * xi1 * xi1;
            float r = (sl * sl) * num * rcp_den * rcp_den;   // = exp(logd)
            if (below) { y = ky[0] + kd[0] * (x - kx[0]); r = kd[0]; }
            if (above) { y = ky[MKNOT - 1] + kd[MKNOT - 1] * (x - kx[MKNOT - 1]); r = kd[MKNOT - 1]; }

            const float t = y - x;
            prod *= r;
            __nv_bfloat16 h = __float2bfloat16(t);
            __nv_bfloat16 l = __float2bfloat16(t - __bfloat162float(h));
            g_t_hi[gidx] = h;
            g_t_lo[gidx] = l;
        }
        g_partial[(size_t)kg * NROWS + n] = logf(prod);
    }
}

__global__ __launch_bounds__(256) void reduce_kernel(float* __restrict__ logj) {
    const int n = blockIdx.x * 256 + threadIdx.x;
    float s = 0.f;
    #pragma unroll
    for (int g = 0; g < 64; ++g) s += g_partial[(size_t)g * NROWS + n];
    logj[n] = s;
}

// ---------------------------------------------------------------------------
extern "C" void kernel_launch(void* const* d_in, const int* in_sizes, int n_in,
                              void* d_out, int out_size) {
    (void)in_sizes; (void)n_in; (void)out_size;
    const float* data  = (const float*)d_in[0];
    const float* A     = (const float*)d_in[1];
    const float* xx    = (const float*)d_in[2];
    const float* yy    = (const float*)d_in[3];
    const float* delta = (const float*)d_in[4];
    float* out  = (float*)d_out;
    float* logj = out + (size_t)NROWS * NDIMS;

    cudaFuncSetAttribute(gemm1_kernel, cudaFuncAttributeMaxDynamicSharedMemorySize, GEMM_SMEM);
    cudaFuncSetAttribute(gemm2_kernel, cudaFuncAttributeMaxDynamicSharedMemorySize, GEMM_SMEM);
    cudaFuncSetAttribute(gemm1_kernel, cudaFuncAttributePreferredSharedMemoryCarveout,
                         cudaSharedmemCarveoutMaxShared);
    cudaFuncSetAttribute(gemm2_kernel, cudaFuncAttributePreferredSharedMemoryCarveout,
                         cudaSharedmemCarveoutMaxShared);

    decomp_data_kernel<<<((size_t)NROWS * NDIMS) / 1024, 256>>>(data);
    decomp_A_kernel<<<(KDIM * NDIMS) / 256, 256>>>(A);
    lut_kernel<<<KDIM, 256>>>(xx);
    gemm1_kernel<<<dim3(4, NROWS / 128), 256, GEMM_SMEM>>>();
    spline_kernel<<<dim3(64, 64), 256>>>(xx, yy, delta);
    reduce_kernel<<<NROWS / 256, 256>>>(logj);
    gemm2_kernel<<<dim3(4, NROWS / 128), 256, GEMM_SMEM>>>(data, out);
}

// round 15
// speedup vs baseline: 1.4734x; 1.4734x over previous
#include <cuda_runtime.h>
#include <cuda_bf16.h>
#include <cstdint>

#define NROWS 65536
#define NDIMS 512
#define KDIM  512
#define MKNOT 200
#define LUTN  1024
#define LUT_SCALE (1024.0f / 12.0f)

// ---------------------------------------------------------------------------
// Device scratch (allocation-free)
// ---------------------------------------------------------------------------
__device__ __align__(16) float         g_x[(size_t)KDIM * NROWS];       // data0^T (K x N)
__device__ __align__(16) __nv_bfloat16 g_data_hi[(size_t)NROWS * NDIMS];
__device__ __align__(16) __nv_bfloat16 g_data_lo[(size_t)NROWS * NDIMS];
__device__ __align__(16) __nv_bfloat16 g_t_hi[(size_t)KDIM * NROWS];    // (K x N)
__device__ __align__(16) __nv_bfloat16 g_t_lo[(size_t)KDIM * NROWS];
__device__ __align__(16) __nv_bfloat16 g_A_hi[KDIM * NDIMS];            // [d][k]
__device__ __align__(16) __nv_bfloat16 g_A_lo[KDIM * NDIMS];
__device__ __align__(16) __nv_bfloat16 g_AT_hi[KDIM * NDIMS];           // [k][d]
__device__ __align__(16) __nv_bfloat16 g_AT_lo[KDIM * NDIMS];
__device__ __align__(16) float         g_partial[64 * NROWS];
__device__ __align__(16) uint8_t       g_lut[(size_t)KDIM * LUTN];

// ---------------------------------------------------------------------------
// PTX helpers (sm_80-level: legal on baseline compute_103 target)
// ---------------------------------------------------------------------------
__device__ __forceinline__ uint32_t smem_u32(const void* p) {
    uint32_t a;
    asm("{ .reg .u64 t; cvta.to.shared.u64 t, %1; cvt.u32.u64 %0, t; }" : "=r"(a) : "l"(p));
    return a;
}
#define CP_ASYNC16(dst, src) \
    asm volatile("cp.async.cg.shared.global [%0], [%1], 16;" :: "r"(dst), "l"(src))
#define CP_COMMIT() asm volatile("cp.async.commit_group;" ::: "memory")
#define CP_WAIT(n)  asm volatile("cp.async.wait_group %0;" :: "n"(n) : "memory")

__device__ __forceinline__ void ldsm_x4(uint32_t* r, uint32_t addr) {
    asm volatile("ldmatrix.sync.aligned.m8n8.x4.shared.b16 {%0,%1,%2,%3}, [%4];"
                 : "=r"(r[0]), "=r"(r[1]), "=r"(r[2]), "=r"(r[3]) : "r"(addr));
}
__device__ __forceinline__ void ldsm_x4_trans(uint32_t* r, uint32_t addr) {
    asm volatile("ldmatrix.sync.aligned.m8n8.x4.trans.shared.b16 {%0,%1,%2,%3}, [%4];"
                 : "=r"(r[0]), "=r"(r[1]), "=r"(r[2]), "=r"(r[3]) : "r"(addr));
}
__device__ __forceinline__ void mma16816(float* d, const uint32_t* a, const uint32_t* b) {
    asm volatile(
        "mma.sync.aligned.m16n8k16.row.col.f32.bf16.bf16.f32 "
        "{%0,%1,%2,%3}, {%4,%5,%6,%7}, {%8,%9}, {%0,%1,%2,%3};"
        : "+f"(d[0]), "+f"(d[1]), "+f"(d[2]), "+f"(d[3])
        : "r"(a[0]), "r"(a[1]), "r"(a[2]), "r"(a[3]), "r"(b[0]), "r"(b[1]));
}

// ---------------------------------------------------------------------------
// Split decomposition
// ---------------------------------------------------------------------------
__global__ __launch_bounds__(256) void decomp_data_kernel(const float* __restrict__ data) {
    size_t i = ((size_t)blockIdx.x * 256 + threadIdx.x) * 4;
    float4 v = *reinterpret_cast<const float4*>(data + i);
    __nv_bfloat16 h0 = __float2bfloat16(v.x), h1 = __float2bfloat16(v.y);
    __nv_bfloat16 h2 = __float2bfloat16(v.z), h3 = __float2bfloat16(v.w);
    __nv_bfloat16 l0 = __float2bfloat16(v.x - __bfloat162float(h0));
    __nv_bfloat16 l1 = __float2bfloat16(v.y - __bfloat162float(h1));
    __nv_bfloat16 l2 = __float2bfloat16(v.z - __bfloat162float(h2));
    __nv_bfloat16 l3 = __float2bfloat16(v.w - __bfloat162float(h3));
    *reinterpret_cast<__nv_bfloat162*>(g_data_hi + i)     = __nv_bfloat162(h0, h1);
    *reinterpret_cast<__nv_bfloat162*>(g_data_hi + i + 2) = __nv_bfloat162(h2, h3);
    *reinterpret_cast<__nv_bfloat162*>(g_data_lo + i)     = __nv_bfloat162(l0, l1);
    *reinterpret_cast<__nv_bfloat162*>(g_data_lo + i + 2) = __nv_bfloat162(l2, l3);
}

__global__ __launch_bounds__(256) void decomp_A_kernel(const float* __restrict__ A) {
    int i = blockIdx.x * 256 + threadIdx.x;
    float v = A[i];
    __nv_bfloat16 h = __float2bfloat16(v);
    __nv_bfloat16 l = __float2bfloat16(v - __bfloat162float(h));
    g_A_hi[i] = h;
    g_A_lo[i] = l;
    int d = i >> 9, k = i & 511;
    g_AT_hi[k * 512 + d] = h;
    g_AT_lo[k * 512 + d] = l;
}

// ---------------------------------------------------------------------------
// LUT build
// ---------------------------------------------------------------------------
__global__ __launch_bounds__(256) void lut_kernel(const float* __restrict__ xx) {
    __shared__ float sx[MKNOT];
    const int k = blockIdx.x;
    const int tid = threadIdx.x;
    if (tid < MKNOT) sx[tid] = xx[(size_t)k * MKNOT + tid];
    __syncthreads();
    for (int j = tid; j < LUTN; j += 256) {
        const float gx = -4.0f + (float)j * (12.0f / LUTN);
        int lo = 0, hi = MKNOT;
        while (lo < hi) {
            int mid = (lo + hi) >> 1;
            if (sx[mid] < gx) lo = mid + 1; else hi = mid;
        }
        g_lut[(size_t)k * LUTN + j] = (uint8_t)lo;
    }
}

// ---------------------------------------------------------------------------
// HMMA GEMM mainloop, phase-paired: D[128,128] over K'=1536 in 16 chunks.
// TB=false: B from (N,K) K-major rows (gemm1, B = AT).
// TB=true : B from (K,N), 64 k-rows x 256B tiles, ldmatrix.trans (gemm2, B = t).
// ---------------------------------------------------------------------------
#define STAGE_BYTES 49152
#define GEMM_SMEM   (2 * STAGE_BYTES)

template <bool TB>
__device__ __forceinline__ void issue_chunk(uint32_t sbase, int buf, int c, int tid,
        const __nv_bfloat16* aHi, const __nv_bfloat16* aLo,
        const __nv_bfloat16* bHi, const __nv_bfloat16* bLo) {
    const bool dual = (c < 8);
    const int koff = (c & 7) * 64;
    const __nv_bfloat16* a = dual ? aHi : aLo;
    uint32_t abase = sbase + buf * STAGE_BYTES;
    uint32_t bbase = abase + 16384;
    #pragma unroll
    for (int it = 0; it < 4; ++it) {          // A tile: 128 rows x 128B (K-major)
        int i = tid + it * 256;
        int r = i >> 3, cc = i & 7;
        CP_ASYNC16(abase + r * 128 + ((cc ^ (r & 7)) << 4),
                   a + (size_t)r * 512 + koff + cc * 8);
    }
    if (!TB) {
        #pragma unroll
        for (int it = 0; it < 4; ++it) {      // B-hi: 128 n-rows x 128B
            int i = tid + it * 256;
            int r = i >> 3, cc = i & 7;
            CP_ASYNC16(bbase + r * 128 + ((cc ^ (r & 7)) << 4),
                       bHi + (size_t)r * 512 + koff + cc * 8);
        }
        if (dual) {
            #pragma unroll
            for (int it = 0; it < 4; ++it) {
                int i = tid + it * 256;
                int r = i >> 3, cc = i & 7;
                CP_ASYNC16(bbase + 16384 + r * 128 + ((cc ^ (r & 7)) << 4),
                           bLo + (size_t)r * 512 + koff + cc * 8);
            }
        }
    } else {
        #pragma unroll
        for (int it = 0; it < 4; ++it) {      // B-hi: 64 k-rows x 256B from (K,N)
            int i = tid + it * 256;
            int r = i >> 4, cc = i & 15;
            CP_ASYNC16(bbase + r * 256 + ((cc ^ (r & 7)) << 4),
                       bHi + (size_t)(koff + r) * NROWS + cc * 8);
        }
        if (dual) {
            #pragma unroll
            for (int it = 0; it < 4; ++it) {
                int i = tid + it * 256;
                int r = i >> 4, cc = i & 15;
                CP_ASYNC16(bbase + 16384 + r * 256 + ((cc ^ (r & 7)) << 4),
                           bLo + (size_t)(koff + r) * NROWS + cc * 8);
            }
        }
    }
}

template <bool TB>
__device__ __forceinline__ void load_bfrag(uint32_t bbase, int s, int lane, int wn,
                                           int grp, uint32_t bf[4][2]) {
    if (!TB) {
        #pragma unroll
        for (int nt2 = 0; nt2 < 2; ++nt2) {
            int rr = wn * 32 + nt2 * 16 + (lane & 7) + ((grp >> 1) << 3);
            int cc = s * 2 + (grp & 1);
            uint32_t tmp[4];
            ldsm_x4(tmp, bbase + rr * 128 + ((cc ^ (rr & 7)) << 4));
            bf[nt2 * 2][0] = tmp[0];     bf[nt2 * 2][1] = tmp[1];
            bf[nt2 * 2 + 1][0] = tmp[2]; bf[nt2 * 2 + 1][1] = tmp[3];
        }
    } else {
        #pragma unroll
        for (int nt2 = 0; nt2 < 2; ++nt2) {
            int rr = s * 16 + ((grp & 1) << 3) + (lane & 7);     // k-row 0..63
            int un = wn * 4 + nt2 * 2 + (grp >> 1);              // 16B n-unit 0..15
            uint32_t tmp[4];
            ldsm_x4_trans(tmp, bbase + rr * 256 + ((un ^ (rr & 7)) << 4));
            bf[nt2 * 2][0] = tmp[0];     bf[nt2 * 2][1] = tmp[1];
            bf[nt2 * 2 + 1][0] = tmp[2]; bf[nt2 * 2 + 1][1] = tmp[3];
        }
    }
}

template <bool TB>
__device__ __forceinline__ void compute_chunk(uint32_t sbase, int buf, bool dual,
                                              int lane, int wm, int wn, float acc[4][4][4]) {
    uint32_t abase = sbase + buf * STAGE_BYTES;
    uint32_t bbase = abase + 16384;
    const int grp = lane >> 3;
    #pragma unroll
    for (int s = 0; s < 4; ++s) {
        uint32_t af[4][4];
        #pragma unroll
        for (int mt = 0; mt < 4; ++mt) {
            int rr = wm * 64 + mt * 16 + (lane & 7) + ((grp & 1) << 3);
            int cc = s * 2 + (grp >> 1);
            ldsm_x4(af[mt], abase + rr * 128 + ((cc ^ (rr & 7)) << 4));
        }
        uint32_t bf[4][2];
        load_bfrag<TB>(bbase, s, lane, wn, grp, bf);
        #pragma unroll
        for (int mt = 0; mt < 4; ++mt)
            #pragma unroll
            for (int nt = 0; nt < 4; ++nt)
                mma16816(acc[mt][nt], af[mt], bf[nt]);
        if (dual) {   // reuse af against the B-lo tile
            uint32_t bf2[4][2];
            load_bfrag<TB>(bbase + 16384, s, lane, wn, grp, bf2);
            #pragma unroll
            for (int mt = 0; mt < 4; ++mt)
                #pragma unroll
                for (int nt = 0; nt < 4; ++nt)
                    mma16816(acc[mt][nt], af[mt], bf2[nt]);
        }
    }
}

template <bool TB>
__device__ __forceinline__ void gemm_mainloop(const __nv_bfloat16* aHi, const __nv_bfloat16* aLo,
                                              const __nv_bfloat16* bHi, const __nv_bfloat16* bLo,
                                              uint32_t sbase, int tid, int lane, int wm, int wn,
                                              float acc[4][4][4]) {
    #pragma unroll
    for (int mt = 0; mt < 4; ++mt)
        #pragma unroll
        for (int nt = 0; nt < 4; ++nt)
            #pragma unroll
            for (int r = 0; r < 4; ++r) acc[mt][nt][r] = 0.f;

    issue_chunk<TB>(sbase, 0, 0, tid, aHi, aLo, bHi, bLo);
    CP_COMMIT();
    int buf = 0;
    for (int c = 0; c < 16; ++c) {
        if (c + 1 < 16) {
            issue_chunk<TB>(sbase, buf ^ 1, c + 1, tid, aHi, aLo, bHi, bLo);
            CP_COMMIT();
            CP_WAIT(1);
        } else {
            CP_WAIT(0);
        }
        __syncthreads();
        compute_chunk<TB>(sbase, buf, c < 8, lane, wm, wn, acc);
        __syncthreads();
        buf ^= 1;
    }
}

// Stage one 64-column half of D into smem as sD[c][m] stride 132.
__device__ __forceinline__ void stage_half(float* sD, const float acc[4][4][4],
                                           int wm, int wn, int lane, int half) {
    if ((wn >> 1) == half) {
        #pragma unroll
        for (int mt = 0; mt < 4; ++mt)
            #pragma unroll
            for (int nt = 0; nt < 4; ++nt) {
                int r0 = wm * 64 + mt * 16 + (lane >> 2);
                int c0 = (wn & 1) * 32 + nt * 8 + (lane & 3) * 2;
                sD[(c0    ) * 132 + r0    ] = acc[mt][nt][0];
                sD[(c0 + 1) * 132 + r0    ] = acc[mt][nt][1];
                sD[(c0    ) * 132 + r0 + 8] = acc[mt][nt][2];
                sD[(c0 + 1) * 132 + r0 + 8] = acc[mt][nt][3];
            }
    }
}

__global__ __launch_bounds__(256, 2) void gemm1_kernel() {
    extern __shared__ char smem[];
    const int k0 = blockIdx.x * 128;
    const int n0 = blockIdx.y * 128;
    const int tid = threadIdx.x;
    const int lane = tid & 31, wid = tid >> 5;
    const int wm = wid & 1, wn = wid >> 1;
    uint32_t sbase = smem_u32(smem);

    float acc[4][4][4];
    gemm_mainloop<false>(g_data_hi + (size_t)n0 * 512, g_data_lo + (size_t)n0 * 512,
                         g_AT_hi + (size_t)k0 * 512, g_AT_lo + (size_t)k0 * 512,
                         sbase, tid, lane, wm, wn, acc);

    float* sD = (float*)smem;
    #pragma unroll
    for (int half = 0; half < 2; ++half) {
        stage_half(sD, acc, wm, wn, lane, half);
        __syncthreads();
        #pragma unroll
        for (int it = 0; it < 8; ++it) {
            int idx = tid + it * 256;
            int nn = idx >> 5, mm = (idx & 31) * 4;
            float4 v = *reinterpret_cast<const float4*>(sD + nn * 132 + mm);
            *reinterpret_cast<float4*>(&g_x[(size_t)(k0 + half * 64 + nn) * NROWS + n0 + mm]) = v;
        }
        __syncthreads();
    }
}

__global__ __launch_bounds__(256, 2) void gemm2_kernel(const float* __restrict__ data,
                                                       float* __restrict__ out) {
    extern __shared__ char smem[];
    const int d0 = blockIdx.x * 128;
    const int n0 = blockIdx.y * 128;
    const int tid = threadIdx.x;
    const int lane = tid & 31, wid = tid >> 5;
    const int wm = wid & 1, wn = wid >> 1;
    uint32_t sbase = smem_u32(smem);

    float acc[4][4][4];
    gemm_mainloop<true>(g_A_hi + (size_t)d0 * 512, g_A_lo + (size_t)d0 * 512,
                        g_t_hi + n0, g_t_lo + n0,
                        sbase, tid, lane, wm, wn, acc);

    float* sD = (float*)smem;
    #pragma unroll
    for (int half = 0; half < 2; ++half) {
        stage_half(sD, acc, wm, wn, lane, half);
        __syncthreads();
        #pragma unroll
        for (int it = 0; it < 8; ++it) {
            int idx = tid + it * 256;
            int nn = idx >> 5, mm = (idx & 31) * 4;
            size_t gi = (size_t)(n0 + half * 64 + nn) * NDIMS + d0 + mm;
            float4 v = *reinterpret_cast<const float4*>(sD + nn * 132 + mm);
            float4 dv = *reinterpret_cast<const float4*>(data + gi);
            v.x += dv.x; v.y += dv.y; v.z += dv.z; v.w += dv.w;
            *reinterpret_cast<float4*>(out + gi) = v;
        }
        __syncthreads();
    }
}

// ---------------------------------------------------------------------------
// Spline v4: block = 8 k x 1024 n (4 s-iters of 256 n, thread = one n, loops k).
// MUFU-lean: reciprocals instead of divides; one logf per 8-k derivative
// product (r_k bounded in ~[0.05, 60] so the 8-product stays in fp32 range).
// ---------------------------------------------------------------------------
__global__ __launch_bounds__(256) void spline_kernel(const float* __restrict__ xx,
                                                     const float* __restrict__ yy,
                                                     const float* __restrict__ delta) {
    __shared__ float sxx[8 * MKNOT], syy[8 * MKNOT], sdl[8 * MKNOT];
    __shared__ uint8_t slut[8 * LUTN];

    const int kg = blockIdx.x;          // 0..63
    const int ng = blockIdx.y;          // 0..63
    const int k0 = kg * 8;
    const int tid = threadIdx.x;

    for (int i = tid; i < 8 * MKNOT; i += 256) {
        int kl = i / MKNOT, m = i - kl * MKNOT;
        size_t gi = (size_t)(k0 + kl) * MKNOT + m;
        sxx[i] = xx[gi]; syy[i] = yy[gi]; sdl[i] = delta[gi];
    }
    for (int i = tid; i < (8 * LUTN) / 4; i += 256)
        reinterpret_cast<uint32_t*>(slut)[i] =
            reinterpret_cast<const uint32_t*>(g_lut + (size_t)k0 * LUTN)[i];
    __syncthreads();

    for (int s = 0; s < 4; ++s) {
        const int n = ng * 1024 + s * 256 + tid;
        float prod = 1.f;
        #pragma unroll 4
        for (int kl = 0; kl < 8; ++kl) {
            const float* kx = sxx + kl * MKNOT;
            const float* ky = syy + kl * MKNOT;
            const float* kd = sdl + kl * MKNOT;
            const size_t gidx = (size_t)(k0 + kl) * NROWS + n;
            const float x = g_x[gidx];

            int j = __float2int_rd((x + 4.0f) * LUT_SCALE);
            j = min(max(j, 0), LUTN - 1);
            int idx = (int)slut[kl * LUTN + j];
            if (idx < MKNOT && kx[idx] < x) ++idx;

            const bool below = (idx == 0);
            const bool above = (idx == MKNOT);
            const int b = min(max(idx, 1), MKNOT - 1) - 1;

            const float xk = kx[b], xk1 = kx[b + 1];
            const float yk = ky[b], yk1 = ky[b + 1];
            const float dk = kd[b], dk1 = kd[b + 1];
            const float dxk = xk1 - xk;
            const float dyk = yk1 - yk;
            const float rcp_dx = __fdividef(1.f, dxk);
            const float sl = dyk * rcp_dx;
            float xi = (x - xk) * rcp_dx;
            xi = fminf(fmaxf(xi, 0.f), 1.f);
            const float xi1 = 1.f - xi;
            const float denom = sl + (dk1 + dk - 2.f * sl) * xi * xi1;
            const float rcp_den = __fdividef(1.f, denom);
            float y = yk + dyk * (sl * xi * xi + dk * xi * xi1) * rcp_den;
            const float num = dk1 * xi * xi + 2.f * sl * xi * xi1 + dk * xi1 * xi1;
            float r = (sl * sl) * num * rcp_den * rcp_den;   // = exp(logd)
            if (below) { y = ky[0] + kd[0] * (x - kx[0]); r = kd[0]; }
            if (above) { y = ky[MKNOT - 1] + kd[MKNOT - 1] * (x - kx[MKNOT - 1]); r = kd[MKNOT - 1]; }

            const float t = y - x;
            prod *= r;
            __nv_bfloat16 h = __float2bfloat16(t);
            __nv_bfloat16 l = __float2bfloat16(t - __bfloat162float(h));
            g_t_hi[gidx] = h;
            g_t_lo[gidx] = l;
        }
        g_partial[(size_t)kg * NROWS + n] = logf(prod);
    }
}

__global__ __launch_bounds__(256) void reduce_kernel(float* __restrict__ logj) {
    const int n = blockIdx.x * 256 + threadIdx.x;
    float s = 0.f;
    #pragma unroll
    for (int g = 0; g < 64; ++g) s += g_partial[(size_t)g * NROWS + n];
    logj[n] = s;
}

// ---------------------------------------------------------------------------
extern "C" void kernel_launch(void* const* d_in, const int* in_sizes, int n_in,
                              void* d_out, int out_size) {
    (void)in_sizes; (void)n_in; (void)out_size;
    const float* data  = (const float*)d_in[0];
    const float* A     = (const float*)d_in[1];
    const float* xx    = (const float*)d_in[2];
    const float* yy    = (const float*)d_in[3];
    const float* delta = (const float*)d_in[4];
    float* out  = (float*)d_out;
    float* logj = out + (size_t)NROWS * NDIMS;

    cudaFuncSetAttribute(gemm1_kernel, cudaFuncAttributeMaxDynamicSharedMemorySize, GEMM_SMEM);
    cudaFuncSetAttribute(gemm2_kernel, cudaFuncAttributeMaxDynamicSharedMemorySize, GEMM_SMEM);
    cudaFuncSetAttribute(gemm1_kernel, cudaFuncAttributePreferredSharedMemoryCarveout,
                         cudaSharedmemCarveoutMaxShared);
    cudaFuncSetAttribute(gemm2_kernel, cudaFuncAttributePreferredSharedMemoryCarveout,
                         cudaSharedmemCarveoutMaxShared);

    decomp_data_kernel<<<((size_t)NROWS * NDIMS) / 1024, 256>>>(data);
    decomp_A_kernel<<<(KDIM * NDIMS) / 256, 256>>>(A);
    lut_kernel<<<KDIM, 256>>>(xx);
    gemm1_kernel<<<dim3(4, NROWS / 128), 256, GEMM_SMEM>>>();
    spline_kernel<<<dim3(64, 64), 256>>>(xx, yy, delta);
    reduce_kernel<<<NROWS / 256, 256>>>(logj);
    gemm2_kernel<<<dim3(4, NROWS / 128), 256, GEMM_SMEM>>>(data, out);
}